// round 2
// baseline (speedup 1.0000x reference)
#include <cuda_runtime.h>
#include <cuda_bf16.h>
#include <math.h>

#define BB 32
#define TT 2048
#define DD 256
#define HH 128

// Scratch for input projection: xp0[t][b][h]
__device__ float g_xp0[(size_t)TT * BB * HH];

// ---------------------------------------------------------------------------
// f32x2 helpers (sm_100+)
// ---------------------------------------------------------------------------
__device__ __forceinline__ unsigned long long pack2(float a, float b) {
    unsigned long long r;
    asm("mov.b64 %0, {%1, %2};" : "=l"(r) : "f"(a), "f"(b));
    return r;
}
__device__ __forceinline__ float2 unpack2(unsigned long long v) {
    float2 r;
    asm("mov.b64 {%0, %1}, %2;" : "=f"(r.x), "=f"(r.y) : "l"(v));
    return r;
}
__device__ __forceinline__ void fma2(unsigned long long& d,
                                     unsigned long long a,
                                     unsigned long long b) {
    asm("fma.rn.f32x2 %0, %1, %2, %0;" : "+l"(d) : "l"(a), "l"(b));
}

// tanh via MUFU.EX2 + MUFU.RCP: abs err ~1e-7, overflow-safe (e->0 => r->1)
__device__ __forceinline__ float fast_tanh(float x) {
    float ax = fabsf(x);
    float e  = __expf(-2.0f * ax);                 // in (0,1]
    float r  = __fdividef(1.0f - e, 1.0f + e);
    return copysignf(r, x);
}

// ---------------------------------------------------------------------------
// Kernel A: xp0[t][b][j] = x[b][t][:] . W_ih0[j][:] + b_ih0[j] + b_hh0[j]
// One block per t, 256 threads. Warp w covers j in [16w,16w+16); lane = b.
// f32x2 over j-pairs; w reads are warp-broadcast LDS (conflict-free),
// x reads pitch-65 (odd stride -> conflict-free).
// ---------------------------------------------------------------------------
__global__ __launch_bounds__(256) void input_proj_kernel(
    const float* __restrict__ x,
    const float* __restrict__ W_ih0,
    const float* __restrict__ b_ih0,
    const float* __restrict__ b_hh0)
{
    __shared__ __align__(16) float xs[BB][65];     // [b][k] pitch 65
    __shared__ __align__(16) float ws[64][HH];     // [k][j]

    const int t    = blockIdx.x;
    const int tid  = threadIdx.x;
    const int w    = tid >> 5;
    const int lane = tid & 31;
    const int jw   = w * 16;     // 16 consecutive outputs per thread
    const int b    = lane;       // batch element per lane

    unsigned long long acc[8];
#pragma unroll
    for (int i = 0; i < 8; i++) acc[i] = 0ull;

    for (int k0 = 0; k0 < DD; k0 += 64) {
        // x tile: 32 b x 64 k  (scalar STS due to odd pitch)
        for (int i = tid; i < BB * 16; i += 256) {
            int bb = i >> 4;
            int kk = (i & 15) * 4;
            float4 v = *(const float4*)&x[((size_t)bb * TT + t) * DD + k0 + kk];
            xs[bb][kk + 0] = v.x; xs[bb][kk + 1] = v.y;
            xs[bb][kk + 2] = v.z; xs[bb][kk + 3] = v.w;
        }
        // w tile transposed: ws[k][j] = W_ih0[j][k0+k]
        for (int i = tid; i < HH * 16; i += 256) {
            int j  = i >> 4;
            int kk = (i & 15) * 4;
            float4 wv = *(const float4*)&W_ih0[(size_t)j * DD + k0 + kk];
            ws[kk + 0][j] = wv.x; ws[kk + 1][j] = wv.y;
            ws[kk + 2][j] = wv.z; ws[kk + 3][j] = wv.w;
        }
        __syncthreads();

#pragma unroll 16
        for (int k = 0; k < 64; k++) {
            ulonglong2 wv0 = *(const ulonglong2*)&ws[k][jw +  0];  // broadcast
            ulonglong2 wv1 = *(const ulonglong2*)&ws[k][jw +  4];
            ulonglong2 wv2 = *(const ulonglong2*)&ws[k][jw +  8];
            ulonglong2 wv3 = *(const ulonglong2*)&ws[k][jw + 12];
            float xv = xs[b][k];
            unsigned long long px = pack2(xv, xv);
            fma2(acc[0], wv0.x, px); fma2(acc[1], wv0.y, px);
            fma2(acc[2], wv1.x, px); fma2(acc[3], wv1.y, px);
            fma2(acc[4], wv2.x, px); fma2(acc[5], wv2.y, px);
            fma2(acc[6], wv3.x, px); fma2(acc[7], wv3.y, px);
        }
        __syncthreads();
    }

    // epilogue: 16 consecutive outputs per thread -> 4 STG.128
    float outv[16];
#pragma unroll
    for (int p = 0; p < 8; p++) {
        float2 f = unpack2(acc[p]);
        outv[2 * p + 0] = f.x + b_ih0[jw + 2 * p + 0] + b_hh0[jw + 2 * p + 0];
        outv[2 * p + 1] = f.y + b_ih0[jw + 2 * p + 1] + b_hh0[jw + 2 * p + 1];
    }
    float* dst = &g_xp0[((size_t)t * BB + b) * HH + jw];
#pragma unroll
    for (int q = 0; q < 4; q++)
        *(float4*)&dst[4 * q] = *(float4*)&outv[4 * q];
}

// ---------------------------------------------------------------------------
// Kernel B: the recurrence. One CTA per batch (32 CTAs), 512 threads.
// tid = j*4 + c: j = tid>>2 in [0,128), c = tid&3 is a 32-wide k-chunk.
// Weight-stationary (96 regs/thread), f32x2 FMAs, quad-shuffle reductions,
// 2 barriers/step. h stored with 36-float chunk pitch -> the 4 per-quad
// float4 LDS addresses hit distinct banks. h0 double-buffered (written
// pre-barrier while old copy is still being read).
// ---------------------------------------------------------------------------
__global__ void __launch_bounds__(512, 1) rnn_rec_kernel(
    const float* __restrict__ W_hh0,
    const float* __restrict__ W_ih1,
    const float* __restrict__ W_hh1,
    const float* __restrict__ b_ih1,
    const float* __restrict__ b_hh1,
    float* __restrict__ out)
{
    const int bidx = blockIdx.x;
    const int tid  = threadIdx.x;
    const int j    = tid >> 2;       // output index
    const int c    = tid & 3;        // k-chunk

    __shared__ __align__(16) float h0buf[2][4 * 36];   // padded: chunk cc at cc*36
    __shared__ __align__(16) float h1buf[4 * 36];

    // register-stationary weights: chunk [c*32, c*32+32) of row j
    ulonglong2 w0[8], w1[8], w2[8];
    {
        const ulonglong2* p0 = (const ulonglong2*)&W_hh0[(size_t)j * HH + c * 32];
        const ulonglong2* p1 = (const ulonglong2*)&W_ih1[(size_t)j * HH + c * 32];
        const ulonglong2* p2 = (const ulonglong2*)&W_hh1[(size_t)j * HH + c * 32];
#pragma unroll
        for (int i = 0; i < 8; i++) { w0[i] = p0[i]; w1[i] = p1[i]; w2[i] = p2[i]; }
    }

    const int posj = (j >> 5) * 36 + (j & 31);   // padded position of h[j]
    const float biasj = b_ih1[j] + b_hh1[j];

    // zero initial state
    for (int i = tid; i < 4 * 36; i += 512) {
        h0buf[0][i] = 0.f;
        h0buf[1][i] = 0.f;
        h1buf[i]    = 0.f;
    }
    __syncthreads();

    const float* xpb  = g_xp0 + (size_t)bidx * HH;
    float*       outb = out + (size_t)bidx * TT * HH;

    float xpr = xpb[j];   // xp for t=0 (quad-broadcast load)

    for (int t = 0; t < TT; t++) {
        const int p = t & 1;
        const float* h0rd = &h0buf[p][c * 36];
        const float* h1rd = &h1buf[c * 36];

        // ---- Phase A: partials of W_hh0.h0 and W_hh1.h1(prev) ----
        unsigned long long acc0 = 0ull, acc1 = 0ull;
#pragma unroll
        for (int i = 0; i < 8; i++) {
            ulonglong2 h = *(const ulonglong2*)(h0rd + i * 4);
            fma2(acc0, w0[i].x, h.x); fma2(acc0, w0[i].y, h.y);
            ulonglong2 g = *(const ulonglong2*)(h1rd + i * 4);
            fma2(acc1, w2[i].x, g.x); fma2(acc1, w2[i].y, g.y);
        }
        float2 f0 = unpack2(acc0); float a0 = f0.x + f0.y;
        float2 f1 = unpack2(acc1); float a1 = f1.x + f1.y;
        a0 += __shfl_xor_sync(0xFFFFFFFFu, a0, 1);
        a0 += __shfl_xor_sync(0xFFFFFFFFu, a0, 2);
        a1 += __shfl_xor_sync(0xFFFFFFFFu, a1, 1);
        a1 += __shfl_xor_sync(0xFFFFFFFFu, a1, 2);

        float h0n = fast_tanh(xpr + a0);
        h0buf[1 - p][posj] = h0n;            // write NEW buffer (no race)
        float s1 = a1 + biasj;               // stays in register across barrier

        // prefetch next xp (value at t=TT-1 wraps but is unused)
        xpr = xpb[(size_t)((t + 1) & (TT - 1)) * BB * HH + j];

        __syncthreads();

        // ---- Phase B: partials of W_ih1.h0n ----
        const float* h0nw = &h0buf[1 - p][c * 36];
        unsigned long long accb = 0ull;
#pragma unroll
        for (int i = 0; i < 8; i++) {
            ulonglong2 h = *(const ulonglong2*)(h0nw + i * 4);
            fma2(accb, w1[i].x, h.x); fma2(accb, w1[i].y, h.y);
        }
        float2 fb = unpack2(accb); float b0 = fb.x + fb.y;
        b0 += __shfl_xor_sync(0xFFFFFFFFu, b0, 1);
        b0 += __shfl_xor_sync(0xFFFFFFFFu, b0, 2);

        float h1n = fast_tanh(s1 + b0);
        h1buf[posj] = h1n;                   // read next step after barrier
        if (c == 0)
            outb[(size_t)t * HH + j] = h1n;

        __syncthreads();
    }
}

// ---------------------------------------------------------------------------
extern "C" void kernel_launch(void* const* d_in, const int* in_sizes, int n_in,
                              void* d_out, int out_size)
{
    const float* x     = (const float*)d_in[0];
    const float* W_ih0 = (const float*)d_in[1];
    const float* W_hh0 = (const float*)d_in[2];
    const float* b_ih0 = (const float*)d_in[3];
    const float* b_hh0 = (const float*)d_in[4];
    const float* W_ih1 = (const float*)d_in[5];
    const float* W_hh1 = (const float*)d_in[6];
    const float* b_ih1 = (const float*)d_in[7];
    const float* b_hh1 = (const float*)d_in[8];
    float* out = (float*)d_out;

    input_proj_kernel<<<TT, 256>>>(x, W_ih0, b_ih0, b_hh0);
    rnn_rec_kernel<<<BB, 512>>>(W_hh0, W_ih1, W_hh1, b_ih1, b_hh1, out);
}